// round 1
// baseline (speedup 1.0000x reference)
#include <cuda_runtime.h>
#include <math.h>

// LearnableTD forward: reverse-time coupled linear recurrence, warp-per-row,
// lane-parallel affine suffix scan over 128-timestep tiles.
//
//   m_t  = gamma*(1-d_t)*lam_t
//   sr_t = r_t + m_t*sr_{t+1}                     (sr_S = 0)
//   lr_t = c_t + m_t*lr_{t+1}                     (lr_S = v_S)
//   c_t  = r_t + gamma*(1-d_t)*(1-lam_t)*v_{t+1}
//
// Outputs: d_out[0:B*S) = lambda_returns, d_out[B*S:2*B*S) = sum_rewards.

constexpr int S_LEN = 1024;            // sequence length (fixed by problem)
constexpr int TILE = 128;              // timesteps per warp iteration (32 lanes * 4)
constexpr int WARPS_PER_BLOCK = 8;
constexpr int THREADS = WARPS_PER_BLOCK * 32;

__global__ void __launch_bounds__(THREADS) td_scan_kernel(
    const float* __restrict__ values,     // B*(S+1)
    const float* __restrict__ rewards,    // B*S
    const float* __restrict__ dones,      // B*S
    const float* __restrict__ raw_gamma,  // 1
    const float* __restrict__ raw_lambd,  // S
    float* __restrict__ out_lambda,       // B*S
    float* __restrict__ out_sumr,         // B*S
    int B)
{
    __shared__ float s_lam[S_LEN];
    const int tid = threadIdx.x;

    // gamma = DF + (1-DF)*(2*sigmoid(rg)-1) = 0.99 + 0.01*tanh(rg/2)
    const float gamma = 0.99f + 0.01f * tanhf(0.5f * __ldg(raw_gamma));
    // lam_t = AL + (1-AL)*(2*sigmoid(rl_t)-1) = 0.95 + 0.05*tanh(rl_t/2)
    for (int i = tid; i < S_LEN; i += THREADS)
        s_lam[i] = 0.95f + 0.05f * tanhf(0.5f * __ldg(raw_lambd + i));
    __syncthreads();

    const int warp = tid >> 5;
    const int lane = tid & 31;
    const int row = blockIdx.x * WARPS_PER_BLOCK + warp;
    if (row >= B) return;

    const float* __restrict__ rrow = rewards + (size_t)row * S_LEN;
    const float* __restrict__ drow = dones   + (size_t)row * S_LEN;
    const float* __restrict__ vrow = values  + (size_t)row * (S_LEN + 1);
    float* __restrict__ lrow = out_lambda + (size_t)row * S_LEN;
    float* __restrict__ srow = out_sumr   + (size_t)row * S_LEN;

    float sr_carry = 0.0f;
    float lr_carry = __ldg(vrow + S_LEN);   // v_S bootstrap (broadcast load)

    #pragma unroll 1
    for (int base = S_LEN - TILE; base >= 0; base -= TILE) {
        const int t0 = base + lane * 4;

        // Coalesced tile loads: lanes cover [base, base+128)
        const float4 r4 = *reinterpret_cast<const float4*>(rrow + t0);
        const float4 d4 = *reinterpret_cast<const float4*>(drow + t0);
        float r[4] = {r4.x, r4.y, r4.z, r4.w};
        float d[4] = {d4.x, d4.y, d4.z, d4.w};

        float m[4], c[4];
        #pragma unroll
        for (int j = 0; j < 4; j++) {
            // v_{t+1}: +1 shift on odd row stride (1025) -> scalar loads
            float v = __ldg(vrow + t0 + j + 1);
            float lam = s_lam[t0 + j];
            float g = gamma * (1.0f - d[j]);
            m[j] = g * lam;
            c[j] = fmaf(g * (1.0f - lam), v, r[j]);
        }

        // Lane-local affine map over its 4 steps (compose j=3..0):
        //   x_start = A + M * x_end   (shared multiplier M for sr and lr)
        float Asr = 0.0f, Alr = 0.0f, M = 1.0f;
        #pragma unroll
        for (int j = 3; j >= 0; j--) {
            Asr = fmaf(m[j], Asr, r[j]);
            Alr = fmaf(m[j], Alr, c[j]);
            M  *= m[j];
        }

        // Inclusive suffix scan across lanes: S_l = f_l o f_{l+1} o ... o f_31
        #pragma unroll
        for (int off = 1; off < 32; off <<= 1) {
            float Asr_o = __shfl_down_sync(0xffffffffu, Asr, off);
            float Alr_o = __shfl_down_sync(0xffffffffu, Alr, off);
            float M_o   = __shfl_down_sync(0xffffffffu, M,   off);
            if (lane + off < 32) {
                Asr = fmaf(M, Asr_o, Asr);
                Alr = fmaf(M, Alr_o, Alr);
                M  *= M_o;
            }
        }

        // Exclusive suffix (carry entering this lane's chunk)
        float eAsr = __shfl_down_sync(0xffffffffu, Asr, 1);
        float eAlr = __shfl_down_sync(0xffffffffu, Alr, 1);
        float eM   = __shfl_down_sync(0xffffffffu, M,   1);
        if (lane == 31) { eAsr = 0.0f; eAlr = 0.0f; eM = 1.0f; }

        float xs = fmaf(eM, sr_carry, eAsr);
        float xl = fmaf(eM, lr_carry, eAlr);

        // Replay the 4 steps to emit per-timestep outputs
        float osr[4], olr[4];
        #pragma unroll
        for (int j = 3; j >= 0; j--) {
            xs = fmaf(m[j], xs, r[j]);
            xl = fmaf(m[j], xl, c[j]);
            osr[j] = xs;
            olr[j] = xl;
        }
        *reinterpret_cast<float4*>(srow + t0) =
            make_float4(osr[0], osr[1], osr[2], osr[3]);
        *reinterpret_cast<float4*>(lrow + t0) =
            make_float4(olr[0], olr[1], olr[2], olr[3]);

        // Tile carry = values at tile start (lane 0, j=0)
        sr_carry = __shfl_sync(0xffffffffu, xs, 0);
        lr_carry = __shfl_sync(0xffffffffu, xl, 0);
    }
}

extern "C" void kernel_launch(void* const* d_in, const int* in_sizes, int n_in,
                              void* d_out, int out_size)
{
    const float* values    = (const float*)d_in[0];
    const float* rewards   = (const float*)d_in[1];
    const float* dones     = (const float*)d_in[2];
    const float* raw_gamma = (const float*)d_in[3];
    const float* raw_lambd = (const float*)d_in[4];

    const int S = in_sizes[4];            // 1024
    const int B = in_sizes[1] / S;        // 32768

    float* out_lambda = (float*)d_out;
    float* out_sumr   = (float*)d_out + (size_t)B * S;

    const int blocks = (B + WARPS_PER_BLOCK - 1) / WARPS_PER_BLOCK;
    td_scan_kernel<<<blocks, THREADS>>>(values, rewards, dones,
                                        raw_gamma, raw_lambd,
                                        out_lambda, out_sumr, B);
}

// round 2
// speedup vs baseline: 1.0379x; 1.0379x over previous
#include <cuda_runtime.h>
#include <math.h>

// LearnableTD forward: reverse-time coupled linear recurrence, warp-per-row,
// lane-parallel affine suffix scan over 128-timestep tiles.
// R2: software-pipelined (double-buffered) tile loads + streaming ld/st hints.
//
//   m_t  = gamma*(1-d_t)*lam_t
//   sr_t = r_t + m_t*sr_{t+1}                     (sr_S = 0)
//   lr_t = c_t + m_t*lr_{t+1}                     (lr_S = v_S)
//   c_t  = r_t + gamma*(1-d_t)*(1-lam_t)*v_{t+1}
//
// Outputs: d_out[0:B*S) = lambda_returns, d_out[B*S:2*B*S) = sum_rewards.

constexpr int S_LEN = 1024;            // sequence length (fixed by problem)
constexpr int TILE = 128;              // timesteps per warp iteration (32 lanes * 4)
constexpr int WARPS_PER_BLOCK = 8;
constexpr int THREADS = WARPS_PER_BLOCK * 32;

__global__ void __launch_bounds__(THREADS) td_scan_kernel(
    const float* __restrict__ values,     // B*(S+1)
    const float* __restrict__ rewards,    // B*S
    const float* __restrict__ dones,      // B*S
    const float* __restrict__ raw_gamma,  // 1
    const float* __restrict__ raw_lambd,  // S
    float* __restrict__ out_lambda,       // B*S
    float* __restrict__ out_sumr,         // B*S
    int B)
{
    __shared__ float s_lam[S_LEN];
    const int tid = threadIdx.x;

    // gamma = DF + (1-DF)*(2*sigmoid(rg)-1) = 0.99 + 0.01*tanh(rg/2)
    const float gamma = 0.99f + 0.01f * tanhf(0.5f * __ldg(raw_gamma));
    // lam_t = AL + (1-AL)*(2*sigmoid(rl_t)-1) = 0.95 + 0.05*tanh(rl_t/2)
    for (int i = tid; i < S_LEN; i += THREADS)
        s_lam[i] = 0.95f + 0.05f * tanhf(0.5f * __ldg(raw_lambd + i));
    __syncthreads();

    const int warp = tid >> 5;
    const int lane = tid & 31;
    const int row = blockIdx.x * WARPS_PER_BLOCK + warp;
    if (row >= B) return;

    const int l4 = lane * 4;
    const float* __restrict__ rrow = rewards + (size_t)row * S_LEN;
    const float* __restrict__ drow = dones   + (size_t)row * S_LEN;
    const float* __restrict__ vrow = values  + (size_t)row * (S_LEN + 1);
    float* __restrict__ lrow = out_lambda + (size_t)row * S_LEN;
    float* __restrict__ srow = out_sumr   + (size_t)row * S_LEN;

    float sr_carry = 0.0f;
    float lr_carry = __ldg(vrow + S_LEN);   // v_S bootstrap (broadcast load)

    // ---- prologue: prefetch the last (first-processed) tile ----
    int base = S_LEN - TILE;
    float4 pr = __ldcs(reinterpret_cast<const float4*>(rrow + base + l4));
    float4 pd = __ldcs(reinterpret_cast<const float4*>(drow + base + l4));
    float pv0 = __ldcs(vrow + base + l4 + 1);
    float pv1 = __ldcs(vrow + base + l4 + 2);
    float pv2 = __ldcs(vrow + base + l4 + 3);
    float pv3 = __ldcs(vrow + base + l4 + 4);

    #pragma unroll 1
    for (; base >= 0; base -= TILE) {
        const int t0 = base + l4;

        // consume the prefetched tile
        float r[4] = {pr.x, pr.y, pr.z, pr.w};
        float d[4] = {pd.x, pd.y, pd.z, pd.w};
        float vv[4] = {pv0, pv1, pv2, pv3};

        // issue next tile's loads BEFORE the scan, so memory latency
        // overlaps the shuffle-dependency chain
        const int nbase = base - TILE;
        if (nbase >= 0) {
            pr = __ldcs(reinterpret_cast<const float4*>(rrow + nbase + l4));
            pd = __ldcs(reinterpret_cast<const float4*>(drow + nbase + l4));
            pv0 = __ldcs(vrow + nbase + l4 + 1);
            pv1 = __ldcs(vrow + nbase + l4 + 2);
            pv2 = __ldcs(vrow + nbase + l4 + 3);
            pv3 = __ldcs(vrow + nbase + l4 + 4);
        }

        float m[4], c[4];
        #pragma unroll
        for (int j = 0; j < 4; j++) {
            float lam = s_lam[t0 + j];
            float g = gamma * (1.0f - d[j]);
            m[j] = g * lam;
            c[j] = fmaf(g * (1.0f - lam), vv[j], r[j]);
        }

        // Lane-local affine map over its 4 steps (compose j=3..0):
        //   x_start = A + M * x_end   (shared multiplier M for sr and lr)
        float Asr = 0.0f, Alr = 0.0f, M = 1.0f;
        #pragma unroll
        for (int j = 3; j >= 0; j--) {
            Asr = fmaf(m[j], Asr, r[j]);
            Alr = fmaf(m[j], Alr, c[j]);
            M  *= m[j];
        }

        // Inclusive suffix scan across lanes: S_l = f_l o f_{l+1} o ... o f_31
        #pragma unroll
        for (int off = 1; off < 32; off <<= 1) {
            float Asr_o = __shfl_down_sync(0xffffffffu, Asr, off);
            float Alr_o = __shfl_down_sync(0xffffffffu, Alr, off);
            float M_o   = __shfl_down_sync(0xffffffffu, M,   off);
            if (lane + off < 32) {
                Asr = fmaf(M, Asr_o, Asr);
                Alr = fmaf(M, Alr_o, Alr);
                M  *= M_o;
            }
        }

        // Exclusive suffix (carry entering this lane's chunk)
        float eAsr = __shfl_down_sync(0xffffffffu, Asr, 1);
        float eAlr = __shfl_down_sync(0xffffffffu, Alr, 1);
        float eM   = __shfl_down_sync(0xffffffffu, M,   1);
        if (lane == 31) { eAsr = 0.0f; eAlr = 0.0f; eM = 1.0f; }

        float xs = fmaf(eM, sr_carry, eAsr);
        float xl = fmaf(eM, lr_carry, eAlr);

        // Replay the 4 steps to emit per-timestep outputs
        float osr[4], olr[4];
        #pragma unroll
        for (int j = 3; j >= 0; j--) {
            xs = fmaf(m[j], xs, r[j]);
            xl = fmaf(m[j], xl, c[j]);
            osr[j] = xs;
            olr[j] = xl;
        }
        __stcs(reinterpret_cast<float4*>(srow + t0),
               make_float4(osr[0], osr[1], osr[2], osr[3]));
        __stcs(reinterpret_cast<float4*>(lrow + t0),
               make_float4(olr[0], olr[1], olr[2], olr[3]));

        // Tile carry = values at tile start (lane 0, j=0)
        sr_carry = __shfl_sync(0xffffffffu, xs, 0);
        lr_carry = __shfl_sync(0xffffffffu, xl, 0);
    }
}

extern "C" void kernel_launch(void* const* d_in, const int* in_sizes, int n_in,
                              void* d_out, int out_size)
{
    const float* values    = (const float*)d_in[0];
    const float* rewards   = (const float*)d_in[1];
    const float* dones     = (const float*)d_in[2];
    const float* raw_gamma = (const float*)d_in[3];
    const float* raw_lambd = (const float*)d_in[4];

    const int S = in_sizes[4];            // 1024
    const int B = in_sizes[1] / S;        // 32768

    float* out_lambda = (float*)d_out;
    float* out_sumr   = (float*)d_out + (size_t)B * S;

    const int blocks = (B + WARPS_PER_BLOCK - 1) / WARPS_PER_BLOCK;
    td_scan_kernel<<<blocks, THREADS>>>(values, rewards, dones,
                                        raw_gamma, raw_lambd,
                                        out_lambda, out_sumr, B);
}